// round 4
// baseline (speedup 1.0000x reference)
#include <cuda_runtime.h>
#include <math.h>

// Problem dims (fixed by the dataset)
#define Bn   4
#define Cn   256
#define HWn  65536
#define Pn   256
#define THRESH_F 0.8f
#define EPSn 1e-5f

typedef unsigned long long ull;

// ---------------------------------------------------------------------------
// Scratch (no cudaMalloc allowed)
// ---------------------------------------------------------------------------
__device__ int   g_idx[Bn * Pn];
__device__ float g_feat[Bn * Pn * Cn];   // (B, P, C)
__device__ float g_z[Bn * Pn * Cn];      // (B, P, C)
__device__ float g_z2[Bn * Pn * Cn];     // (B, P, C) : z2[p][c]

// topk scratch: one 65536-bin histogram per (pass, batch); 3 passes
__device__ unsigned int g_hist[3][Bn][65536];   // 3 MB
__device__ ull g_prefix[Bn];
__device__ int g_K[Bn];
__device__ int g_candcnt[Bn];
__device__ ull g_cand[Bn][Pn];

// ---------------------------------------------------------------------------
// 48-bit composite key: (monotone_float32 << 16) | (0xFFFF - idx)
// idx < 65536 fits exactly in 16 bits. Larger key == larger value;
// ties -> smaller index wins. Keys are unique.
// ---------------------------------------------------------------------------
__device__ __forceinline__ ull make_key(float e, int i) {
    float v = (e < THRESH_F) ? 0.0f : e;
    unsigned int ub = __float_as_uint(v);
    ub = (ub & 0x80000000u) ? ~ub : (ub | 0x80000000u);
    return ((ull)ub << 16) | (ull)(0xFFFFu - (unsigned int)i);
}

// ---------------------------------------------------------------------------
// SM bulk copy: out <- x  (256 MB). float4 grid-stride.
// ---------------------------------------------------------------------------
__global__ void __launch_bounds__(256)
copy_kernel(const float4* __restrict__ src, float4* __restrict__ dst) {
    const int n4 = Bn * Cn * HWn / 4;   // 16,777,216
    int i = blockIdx.x * blockDim.x + threadIdx.x;
    const int stride = gridDim.x * blockDim.x;
    for (; i < n4; i += stride) dst[i] = src[i];
}

// ---------------------------------------------------------------------------
// topk init: zero histograms, reset per-batch select state.
// ---------------------------------------------------------------------------
__global__ void topk_init() {
    const int tid = blockIdx.x * blockDim.x + threadIdx.x;
    unsigned int* h = &g_hist[0][0][0];
    const int total = 3 * Bn * 65536;
    for (int i = tid; i < total; i += gridDim.x * blockDim.x) h[i] = 0u;
    if (tid < Bn) {
        g_prefix[tid] = 0ull;
        g_K[tid] = Pn;
        g_candcnt[tid] = 0;
    }
}

// ---------------------------------------------------------------------------
// One radix pass histogram (16-bit digit). grid = (64, Bn), 1024 threads.
// pass = 2 (float hi16) .. 0 (inverted-index 16).
// ---------------------------------------------------------------------------
__global__ void __launch_bounds__(1024)
topk_hist(const float* __restrict__ edge, int pass) {
    const int b = blockIdx.y;
    const int i = blockIdx.x * 1024 + threadIdx.x;
    const ull key = make_key(edge[(size_t)b * HWn + i], i);

    bool active;
    if (pass == 2) {
        active = true;
    } else {
        const ull pre = g_prefix[b];
        active = ((key >> ((pass + 1) * 16)) == pre);
    }
    const unsigned int bin = (unsigned int)((key >> (pass * 16)) & 0xFFFFull);
    const unsigned int amask = __ballot_sync(0xFFFFFFFFu, active);
    if (active) {
        const unsigned int peers = __match_any_sync(amask, bin);
        const int leader = __ffs(peers) - 1;
        if ((int)(threadIdx.x & 31) == leader)
            atomicAdd(&g_hist[pass][b][bin], (unsigned int)__popc(peers));
    }
}

// ---------------------------------------------------------------------------
// Select the digit containing rank K (descending). grid = Bn, 1024 threads.
// Two-phase: (1) shuffle-based suffix scan over 1024 chunk sums to find the
// 64-bin chunk containing rank K; (2) parallel load of that chunk's 64 bins
// into smem + mini suffix scan to find the exact digit. No serial global
// pointer-chases.
// ---------------------------------------------------------------------------
__global__ void __launch_bounds__(1024, 1)
topk_scan(int pass) {
    const int b = blockIdx.x;
    const unsigned int* hist = g_hist[pass][b];
    const int t = threadIdx.x;
    const int lane = t & 31;
    const int w = t >> 5;

    __shared__ unsigned int warpsum[32];
    __shared__ unsigned int warpsuf[32];   // exclusive suffix over warps
    __shared__ int sh_chunk;
    __shared__ unsigned int sh_krem;
    __shared__ unsigned int bins[64];
    __shared__ unsigned int binsuf[64];

    // Phase 1a: per-thread partial sum over 64 bins (parallel loads).
    unsigned int mine = 0;
    #pragma unroll 8
    for (int j = 0; j < 64; ++j) mine += hist[t * 64 + j];

    // Phase 1b: warp-level inclusive suffix sum (sum over lanes >= lane).
    unsigned int suf = mine;
    #pragma unroll
    for (int off = 1; off < 32; off <<= 1) {
        const unsigned int v = __shfl_down_sync(0xFFFFFFFFu, suf, off);
        if (lane + off < 32) suf += v;
    }
    if (lane == 0) warpsum[w] = suf;   // warp total
    __syncthreads();

    // Phase 1c: warp 0 computes exclusive suffix over the 32 warp totals.
    if (w == 0) {
        unsigned int ws = warpsum[lane];
        unsigned int wsuf = ws;
        #pragma unroll
        for (int off = 1; off < 32; off <<= 1) {
            const unsigned int v = __shfl_down_sync(0xFFFFFFFFu, wsuf, off);
            if (lane + off < 32) wsuf += v;
        }
        warpsuf[lane] = wsuf - ws;     // strictly-greater warps
    }
    __syncthreads();

    const unsigned int K = (unsigned int)g_K[b];
    const unsigned int suf_t = suf + warpsuf[w];   // sum over chunks >= t
    const unsigned int above = suf_t - mine;       // sum over chunks  > t
    if (suf_t >= K && above < K) {
        sh_chunk = t;
        sh_krem = K - above;
    }
    __syncthreads();

    // Phase 2: resolve the digit inside the selected 64-bin chunk.
    const int chunk = sh_chunk;
    if (t < 64) bins[t] = hist[chunk * 64 + t];
    __syncthreads();

    if (w < 2) {   // threads 0..63
        // inclusive suffix sum over 64 bins (2 warps + one cross-warp fix)
        unsigned int s = bins[t];
        unsigned int ss = s;
        #pragma unroll
        for (int off = 1; off < 32; off <<= 1) {
            const unsigned int v = __shfl_down_sync(0xFFFFFFFFu, ss, off);
            if (lane + off < 32) ss += v;
        }
        binsuf[t] = ss;
        __syncwarp();
        if (w == 0) {
            // add warp-1 total to warp-0 suffixes
            const unsigned int w1tot = binsuf[32];
            binsuf[t] = ss + w1tot;
        }
    }
    __syncthreads();

    if (t < 64) {
        const unsigned int krem = sh_krem;
        const unsigned int st = binsuf[t];
        const unsigned int ab = st - bins[t];
        if (st >= krem && ab < krem) {
            g_prefix[b] = (g_prefix[b] << 16) | (ull)(chunk * 64 + t);
            g_K[b] = (int)(krem - ab);
        }
    }
}

// ---------------------------------------------------------------------------
// Collect the exact top-256 keys (key >= exact cutoff key). grid=(64,Bn).
// ---------------------------------------------------------------------------
__global__ void __launch_bounds__(1024)
topk_collect(const float* __restrict__ edge) {
    const int b = blockIdx.y;
    const int i = blockIdx.x * 1024 + threadIdx.x;
    const ull key = make_key(edge[(size_t)b * HWn + i], i);
    const ull cutoff = g_prefix[b];
    if (key >= cutoff) {
        const int p = atomicAdd(&g_candcnt[b], 1);
        g_cand[b][p] = key;   // exactly 256 per batch (keys unique)
    }
}

// ---------------------------------------------------------------------------
// Bitonic sort 256 keys descending -> g_idx. grid=Bn, 256 threads.
// ---------------------------------------------------------------------------
__global__ void __launch_bounds__(256, 1)
topk_sort() {
    const int b = blockIdx.x;
    __shared__ ull keys[Pn];
    keys[threadIdx.x] = g_cand[b][threadIdx.x];
    __syncthreads();

    for (int kk = 2; kk <= Pn; kk <<= 1) {
        for (int jj = kk >> 1; jj > 0; jj >>= 1) {
            const int i = threadIdx.x;
            const int ixj = i ^ jj;
            if (ixj > i) {
                const ull a = keys[i];
                const ull c = keys[ixj];
                const bool up = ((i & kk) == 0);
                const bool sw = up ? (a < c) : (a > c);
                if (sw) { keys[i] = c; keys[ixj] = a; }
            }
            __syncthreads();
        }
    }
    g_idx[b * Pn + threadIdx.x] =
        (int)(0xFFFFu - (unsigned int)(keys[threadIdx.x] & 0xFFFFull));
}

// ---------------------------------------------------------------------------
// Gather: feat[b][n][d] = x[b][d][idx[b][n]]   grid (Pn, Bn), 256 threads (d)
// ---------------------------------------------------------------------------
__global__ void gather_kernel(const float* __restrict__ x) {
    const int b = blockIdx.y;
    const int n = blockIdx.x;
    const int d = threadIdx.x;
    const int col = g_idx[b * Pn + n];
    g_feat[((b * Pn + n) << 8) + d] =
        x[(size_t)b * Cn * HWn + (size_t)d * HWn + (size_t)col];
}

// ---------------------------------------------------------------------------
// GEMM1 (NN): Z[b,i,d] = relu(BN_adj(sum_j W_adj[i,j]*feat[b,j,d])) + feat[b,i,d]
// ---------------------------------------------------------------------------
__global__ void __launch_bounds__(256)
gemm1_kernel(const float* __restrict__ W,
             const float* __restrict__ ga, const float* __restrict__ ba,
             const float* __restrict__ ma, const float* __restrict__ va) {
    __shared__ float sA[16][64 + 4];
    __shared__ float sB[16][64 + 4];

    const int b  = blockIdx.z;
    const float* F = g_feat + b * Pn * Cn;
    float* Z       = g_z    + b * Pn * Cn;
    const int ti = blockIdx.y * 64;
    const int td = blockIdx.x * 64;
    const int tx = threadIdx.x & 15;
    const int ty = threadIdx.x >> 4;

    float acc[4][4] = {};

    for (int k0 = 0; k0 < Pn; k0 += 16) {
        #pragma unroll
        for (int r = 0; r < 4; ++r) {
            const int eI = threadIdx.x + r * 256;
            const int ai = eI >> 4, ak = eI & 15;
            sA[ak][ai] = W[(ti + ai) * Pn + (k0 + ak)];
            const int bk = eI >> 6, bd = eI & 63;
            sB[bk][bd] = F[(k0 + bk) * Cn + (td + bd)];
        }
        __syncthreads();
        #pragma unroll
        for (int k = 0; k < 16; ++k) {
            float a0[4], b0[4];
            #pragma unroll
            for (int u = 0; u < 4; ++u) a0[u] = sA[k][ty * 4 + u];
            #pragma unroll
            for (int u = 0; u < 4; ++u) b0[u] = sB[k][tx * 4 + u];
            #pragma unroll
            for (int i = 0; i < 4; ++i)
                #pragma unroll
                for (int j = 0; j < 4; ++j)
                    acc[i][j] += a0[i] * b0[j];
        }
        __syncthreads();
    }

    #pragma unroll
    for (int ui = 0; ui < 4; ++ui) {
        const int i = ti + ty * 4 + ui;
        const float inv = ga[i] * rsqrtf(va[i] + EPSn);
        const float add = ba[i] - ma[i] * inv;
        #pragma unroll
        for (int ud = 0; ud < 4; ++ud) {
            const int d = td + tx * 4 + ud;
            Z[i * Cn + d] = fmaxf(acc[ui][ud] * inv + add, 0.0f) + F[i * Cn + d];
        }
    }
}

// ---------------------------------------------------------------------------
// GEMM2 compute (NT): z2[b,p,c] = relu(BN_wg(sum_d Z[b,p,d]*W_wg[c,d]))
// ---------------------------------------------------------------------------
__global__ void __launch_bounds__(256)
gemm2_kernel(const float* __restrict__ Wg,
             const float* __restrict__ gw, const float* __restrict__ bw,
             const float* __restrict__ mw, const float* __restrict__ vw) {
    __shared__ float sA[16][64 + 4];
    __shared__ float sB[16][64 + 4];

    const int b = blockIdx.z;
    const float* Z = g_z  + b * Pn * Cn;
    float* Z2      = g_z2 + b * Pn * Cn;
    const int tp = blockIdx.y * 64;
    const int tc = blockIdx.x * 64;
    const int tx = threadIdx.x & 15;
    const int ty = threadIdx.x >> 4;

    float acc[4][4] = {};

    for (int k0 = 0; k0 < Cn; k0 += 16) {
        #pragma unroll
        for (int r = 0; r < 4; ++r) {
            const int eI = threadIdx.x + r * 256;
            const int ar = eI >> 4, ak = eI & 15;
            sA[ak][ar] = Z[(tp + ar) * Cn + (k0 + ak)];
            sB[ak][ar] = Wg[(tc + ar) * Cn + (k0 + ak)];
        }
        __syncthreads();
        #pragma unroll
        for (int k = 0; k < 16; ++k) {
            float a0[4], b0[4];
            #pragma unroll
            for (int u = 0; u < 4; ++u) a0[u] = sA[k][ty * 4 + u];
            #pragma unroll
            for (int u = 0; u < 4; ++u) b0[u] = sB[k][tx * 4 + u];
            #pragma unroll
            for (int i = 0; i < 4; ++i)
                #pragma unroll
                for (int j = 0; j < 4; ++j)
                    acc[i][j] += a0[i] * b0[j];
        }
        __syncthreads();
    }

    #pragma unroll
    for (int uc = 0; uc < 4; ++uc) {
        const int c = tc + tx * 4 + uc;
        const float inv = gw[c] * rsqrtf(vw[c] + EPSn);
        const float add = bw[c] - mw[c] * inv;
        #pragma unroll
        for (int ui = 0; ui < 4; ++ui) {
            const int p = tp + ty * 4 + ui;
            Z2[p * Cn + c] = fmaxf(acc[ui][uc] * inv + add, 0.0f);
        }
    }
}

// ---------------------------------------------------------------------------
// Scatter: out[b, c, idx[b,p]] = z2[b,p,c].  grid (Pn, Bn), 256 threads (c).
// ---------------------------------------------------------------------------
__global__ void __launch_bounds__(256)
scatter_kernel(float* __restrict__ out) {
    const int b = blockIdx.y;
    const int p = blockIdx.x;
    const int c = threadIdx.x;
    const int col = g_idx[b * Pn + p];
    out[(size_t)b * Cn * HWn + (size_t)c * HWn + (size_t)col] =
        g_z2[((b * Pn + p) << 8) + c];
}

// ---------------------------------------------------------------------------
extern "C" void kernel_launch(void* const* d_in, const int* in_sizes, int n_in,
                              void* d_out, int out_size) {
    const float* x     = (const float*)d_in[0];
    const float* edge  = (const float*)d_in[1];
    const float* w_adj = (const float*)d_in[2];
    const float* g_adj = (const float*)d_in[3];
    const float* b_adj = (const float*)d_in[4];
    const float* m_adj = (const float*)d_in[5];
    const float* v_adj = (const float*)d_in[6];
    const float* w_wg  = (const float*)d_in[7];
    const float* g_wg  = (const float*)d_in[8];
    const float* b_wg  = (const float*)d_in[9];
    const float* m_wg  = (const float*)d_in[10];
    const float* v_wg  = (const float*)d_in[11];
    float* out = (float*)d_out;

    static cudaStream_t s1 = nullptr;
    static cudaEvent_t evA = nullptr, evB = nullptr;
    if (s1 == nullptr) {
        cudaStreamCreateWithFlags(&s1, cudaStreamNonBlocking);
        cudaEventCreateWithFlags(&evA, cudaEventDisableTiming);
        cudaEventCreateWithFlags(&evB, cudaEventDisableTiming);
    }

    // Fork side stream from stream 0.
    cudaEventRecord(evA, 0);
    cudaStreamWaitEvent(s1, evA, 0);

    // Stream 0: bulk copy x -> out on the SMs (not the copy engine).
    copy_kernel<<<2048, 256>>>((const float4*)x, (float4*)out);

    // Side stream: exact top-256 via 3x16-bit radix select (chip-wide).
    topk_init<<<192, 1024, 0, s1>>>();
    for (int pass = 2; pass >= 0; --pass) {
        topk_hist<<<dim3(64, Bn), 1024, 0, s1>>>(edge, pass);
        topk_scan<<<Bn, 1024, 0, s1>>>(pass);
    }
    topk_collect<<<dim3(64, Bn), 1024, 0, s1>>>(edge);
    topk_sort<<<Bn, 256, 0, s1>>>();

    // Side stream: gather + GCN stage 1 + GCN stage 2 compute.
    gather_kernel<<<dim3(Pn, Bn), Cn, 0, s1>>>(x);
    gemm1_kernel<<<dim3(4, 4, Bn), 256, 0, s1>>>(w_adj, g_adj, b_adj, m_adj, v_adj);
    gemm2_kernel<<<dim3(4, 4, Bn), 256, 0, s1>>>(w_wg, g_wg, b_wg, m_wg, v_wg);

    // Join and scatter the reasoned point features into out.
    cudaEventRecord(evB, s1);
    cudaStreamWaitEvent(0, evB, 0);
    scatter_kernel<<<dim3(Pn, Bn), 256>>>(out);
}

// round 5
// speedup vs baseline: 2.1600x; 2.1600x over previous
#include <cuda_runtime.h>
#include <math.h>

// Problem dims (fixed by the dataset)
#define Bn   4
#define Cn   256
#define HWn  65536
#define Pn   256
#define THRESH_F 0.8f
#define EPSn 1e-5f

typedef unsigned long long ull;

// ---------------------------------------------------------------------------
// Scratch (no cudaMalloc allowed)
// ---------------------------------------------------------------------------
__device__ int   g_idx[Bn * Pn];
__device__ float g_feat[Bn * Pn * Cn];   // (B, P, C)
__device__ float g_z[Bn * Pn * Cn];      // (B, P, C)
__device__ float g_z2[Bn * Pn * Cn];     // (B, P, C) : z2[p][c]

// topk scratch: fine (65536-bin) + coarse (1024-bin) histograms per (pass, b)
__device__ unsigned int g_hist[3][Bn][65536];    // 3 MB
__device__ unsigned int g_coarse[3][Bn][1024];   // 48 KB
__device__ ull g_prefix[Bn];
__device__ int g_K[Bn];
__device__ int g_candcnt[Bn];
__device__ ull g_cand[Bn][Pn];

// ---------------------------------------------------------------------------
// 48-bit composite key: (monotone_float32 << 16) | (0xFFFF - idx)
// idx < 65536 fits exactly in 16 bits. Larger key == larger value;
// ties -> smaller index wins. Keys are unique.
// ---------------------------------------------------------------------------
__device__ __forceinline__ ull make_key(float e, int i) {
    float v = (e < THRESH_F) ? 0.0f : e;
    unsigned int ub = __float_as_uint(v);
    ub = (ub & 0x80000000u) ? ~ub : (ub | 0x80000000u);
    return ((ull)ub << 16) | (ull)(0xFFFFu - (unsigned int)i);
}

// ---------------------------------------------------------------------------
// SM bulk copy: out <- x  (256 MB). float4 grid-stride.
// ---------------------------------------------------------------------------
__global__ void __launch_bounds__(256)
copy_kernel(const float4* __restrict__ src, float4* __restrict__ dst) {
    const int n4 = Bn * Cn * HWn / 4;   // 16,777,216
    int i = blockIdx.x * blockDim.x + threadIdx.x;
    const int stride = gridDim.x * blockDim.x;
    for (; i < n4; i += stride) dst[i] = src[i];
}

// ---------------------------------------------------------------------------
// topk init: zero histograms, reset per-batch select state.
// ---------------------------------------------------------------------------
__global__ void topk_init() {
    const int tid = blockIdx.x * blockDim.x + threadIdx.x;
    unsigned int* h = &g_hist[0][0][0];
    const int total = 3 * Bn * 65536;
    for (int i = tid; i < total; i += gridDim.x * blockDim.x) h[i] = 0u;
    unsigned int* c = &g_coarse[0][0][0];
    const int totalc = 3 * Bn * 1024;
    for (int i = tid; i < totalc; i += gridDim.x * blockDim.x) c[i] = 0u;
    if (tid < Bn) {
        g_prefix[tid] = 0ull;
        g_K[tid] = Pn;
        g_candcnt[tid] = 0;
    }
}

// ---------------------------------------------------------------------------
// One radix pass histogram (16-bit digit), fine + coarse.
// grid = (64, Bn), 1024 threads.  pass = 2 (float hi16) .. 0 (inv-index 16).
// ---------------------------------------------------------------------------
__global__ void __launch_bounds__(1024)
topk_hist(const float* __restrict__ edge, int pass) {
    const int b = blockIdx.y;
    const int i = blockIdx.x * 1024 + threadIdx.x;
    const ull key = make_key(edge[(size_t)b * HWn + i], i);

    bool active;
    if (pass == 2) {
        active = true;
    } else {
        const ull pre = g_prefix[b];
        active = ((key >> ((pass + 1) * 16)) == pre);
    }
    const unsigned int bin = (unsigned int)((key >> (pass * 16)) & 0xFFFFull);
    const unsigned int amask = __ballot_sync(0xFFFFFFFFu, active);
    if (active) {
        const int lane = (int)(threadIdx.x & 31);
        // fine
        unsigned int peers = __match_any_sync(amask, bin);
        if (lane == __ffs(peers) - 1)
            atomicAdd(&g_hist[pass][b][bin], (unsigned int)__popc(peers));
        // coarse (bin >> 6)
        unsigned int peersc = __match_any_sync(amask, bin >> 6);
        if (lane == __ffs(peersc) - 1)
            atomicAdd(&g_coarse[pass][b][bin >> 6], (unsigned int)__popc(peersc));
    }
}

// ---------------------------------------------------------------------------
// Select the digit containing rank K (descending). grid = Bn, 1024 threads.
// Phase 1: one coalesced coarse load per thread + shuffle suffix scan finds
// the 64-bin chunk. Phase 2: 64 coalesced fine loads + single-warp suffix
// scan finds the exact digit.
// ---------------------------------------------------------------------------
__global__ void __launch_bounds__(1024, 1)
topk_scan(int pass) {
    const int b = blockIdx.x;
    const int t = threadIdx.x;
    const int lane = t & 31;
    const int w = t >> 5;

    __shared__ unsigned int warpsum[32];
    __shared__ unsigned int warpsuf[32];
    __shared__ int sh_chunk;
    __shared__ unsigned int sh_krem;
    __shared__ unsigned int bins[64];

    // Phase 1a: coalesced coarse chunk sum.
    const unsigned int mine = g_coarse[pass][b][t];

    // Phase 1b: warp inclusive suffix sum.
    unsigned int suf = mine;
    #pragma unroll
    for (int off = 1; off < 32; off <<= 1) {
        const unsigned int v = __shfl_down_sync(0xFFFFFFFFu, suf, off);
        if (lane + off < 32) suf += v;
    }
    if (lane == 0) warpsum[w] = suf;
    __syncthreads();

    // Phase 1c: warp 0 -> exclusive suffix over warp totals.
    if (w == 0) {
        const unsigned int ws = warpsum[lane];
        unsigned int wsuf = ws;
        #pragma unroll
        for (int off = 1; off < 32; off <<= 1) {
            const unsigned int v = __shfl_down_sync(0xFFFFFFFFu, wsuf, off);
            if (lane + off < 32) wsuf += v;
        }
        warpsuf[lane] = wsuf - ws;
    }
    __syncthreads();

    const unsigned int K = (unsigned int)g_K[b];
    const unsigned int suf_t = suf + warpsuf[w];   // sum over chunks >= t
    const unsigned int above = suf_t - mine;       // sum over chunks  > t
    if (suf_t >= K && above < K) {
        sh_chunk = t;
        sh_krem = K - above;
    }
    __syncthreads();

    // Phase 2: resolve digit inside the 64-bin chunk (coalesced loads).
    const int chunk = sh_chunk;
    if (t < 64) bins[t] = g_hist[pass][b][chunk * 64 + t];
    __syncthreads();

    if (w == 0) {  // single warp, race-free
        const unsigned int krem = sh_krem;
        const unsigned int lo = bins[lane];
        const unsigned int hi = bins[lane + 32];

        unsigned int suf_hi = hi;
        #pragma unroll
        for (int off = 1; off < 32; off <<= 1) {
            const unsigned int v = __shfl_down_sync(0xFFFFFFFFu, suf_hi, off);
            if (lane + off < 32) suf_hi += v;
        }
        const unsigned int hi_total = __shfl_sync(0xFFFFFFFFu, suf_hi, 0);

        unsigned int suf_lo = lo;
        #pragma unroll
        for (int off = 1; off < 32; off <<= 1) {
            const unsigned int v = __shfl_down_sync(0xFFFFFFFFu, suf_lo, off);
            if (lane + off < 32) suf_lo += v;
        }
        suf_lo += hi_total;   // suffix including the whole hi half

        // hi half digits: chunk*64 + 32 + lane
        {
            const unsigned int st = suf_hi, ab = st - hi;
            if (st >= krem && ab < krem) {
                g_prefix[b] = (g_prefix[b] << 16) | (ull)(chunk * 64 + 32 + lane);
                g_K[b] = (int)(krem - ab);
            }
        }
        // lo half digits: chunk*64 + lane
        {
            const unsigned int st = suf_lo, ab = st - lo;
            if (st >= krem && ab < krem) {
                g_prefix[b] = (g_prefix[b] << 16) | (ull)(chunk * 64 + lane);
                g_K[b] = (int)(krem - ab);
            }
        }
    }
}

// ---------------------------------------------------------------------------
// Collect the exact top-256 keys (key >= exact cutoff key). grid=(64,Bn).
// ---------------------------------------------------------------------------
__global__ void __launch_bounds__(1024)
topk_collect(const float* __restrict__ edge) {
    const int b = blockIdx.y;
    const int i = blockIdx.x * 1024 + threadIdx.x;
    const ull key = make_key(edge[(size_t)b * HWn + i], i);
    const ull cutoff = g_prefix[b];
    if (key >= cutoff) {
        const int p = atomicAdd(&g_candcnt[b], 1);
        g_cand[b][p] = key;   // exactly 256 per batch (keys unique)
    }
}

// ---------------------------------------------------------------------------
// Bitonic sort 256 keys descending -> g_idx. grid=Bn, 256 threads.
// ---------------------------------------------------------------------------
__global__ void __launch_bounds__(256, 1)
topk_sort() {
    const int b = blockIdx.x;
    __shared__ ull keys[Pn];
    keys[threadIdx.x] = g_cand[b][threadIdx.x];
    __syncthreads();

    for (int kk = 2; kk <= Pn; kk <<= 1) {
        for (int jj = kk >> 1; jj > 0; jj >>= 1) {
            const int i = threadIdx.x;
            const int ixj = i ^ jj;
            if (ixj > i) {
                const ull a = keys[i];
                const ull c = keys[ixj];
                const bool up = ((i & kk) == 0);
                const bool sw = up ? (a < c) : (a > c);
                if (sw) { keys[i] = c; keys[ixj] = a; }
            }
            __syncthreads();
        }
    }
    g_idx[b * Pn + threadIdx.x] =
        (int)(0xFFFFu - (unsigned int)(keys[threadIdx.x] & 0xFFFFull));
}

// ---------------------------------------------------------------------------
// Gather: feat[b][n][d] = x[b][d][idx[b][n]]   grid (Pn, Bn), 256 threads (d)
// ---------------------------------------------------------------------------
__global__ void gather_kernel(const float* __restrict__ x) {
    const int b = blockIdx.y;
    const int n = blockIdx.x;
    const int d = threadIdx.x;
    const int col = g_idx[b * Pn + n];
    g_feat[((b * Pn + n) << 8) + d] =
        x[(size_t)b * Cn * HWn + (size_t)d * HWn + (size_t)col];
}

// ---------------------------------------------------------------------------
// GEMM1 (NN): Z[b,i,d] = relu(BN_adj(sum_j W_adj[i,j]*feat[b,j,d])) + feat[b,i,d]
// ---------------------------------------------------------------------------
__global__ void __launch_bounds__(256)
gemm1_kernel(const float* __restrict__ W,
             const float* __restrict__ ga, const float* __restrict__ ba,
             const float* __restrict__ ma, const float* __restrict__ va) {
    __shared__ float sA[16][64 + 4];
    __shared__ float sB[16][64 + 4];

    const int b  = blockIdx.z;
    const float* F = g_feat + b * Pn * Cn;
    float* Z       = g_z    + b * Pn * Cn;
    const int ti = blockIdx.y * 64;
    const int td = blockIdx.x * 64;
    const int tx = threadIdx.x & 15;
    const int ty = threadIdx.x >> 4;

    float acc[4][4] = {};

    for (int k0 = 0; k0 < Pn; k0 += 16) {
        #pragma unroll
        for (int r = 0; r < 4; ++r) {
            const int eI = threadIdx.x + r * 256;
            const int ai = eI >> 4, ak = eI & 15;
            sA[ak][ai] = W[(ti + ai) * Pn + (k0 + ak)];
            const int bk = eI >> 6, bd = eI & 63;
            sB[bk][bd] = F[(k0 + bk) * Cn + (td + bd)];
        }
        __syncthreads();
        #pragma unroll
        for (int k = 0; k < 16; ++k) {
            const float4 a4 = *(const float4*)&sA[k][ty * 4];
            const float4 b4 = *(const float4*)&sB[k][tx * 4];
            const float a0[4] = {a4.x, a4.y, a4.z, a4.w};
            const float b0[4] = {b4.x, b4.y, b4.z, b4.w};
            #pragma unroll
            for (int i = 0; i < 4; ++i)
                #pragma unroll
                for (int j = 0; j < 4; ++j)
                    acc[i][j] += a0[i] * b0[j];
        }
        __syncthreads();
    }

    #pragma unroll
    for (int ui = 0; ui < 4; ++ui) {
        const int i = ti + ty * 4 + ui;
        const float inv = ga[i] * rsqrtf(va[i] + EPSn);
        const float add = ba[i] - ma[i] * inv;
        #pragma unroll
        for (int ud = 0; ud < 4; ++ud) {
            const int d = td + tx * 4 + ud;
            Z[i * Cn + d] = fmaxf(acc[ui][ud] * inv + add, 0.0f) + F[i * Cn + d];
        }
    }
}

// ---------------------------------------------------------------------------
// GEMM2 compute (NT): z2[b,p,c] = relu(BN_wg(sum_d Z[b,p,d]*W_wg[c,d]))
// ---------------------------------------------------------------------------
__global__ void __launch_bounds__(256)
gemm2_kernel(const float* __restrict__ Wg,
             const float* __restrict__ gw, const float* __restrict__ bw,
             const float* __restrict__ mw, const float* __restrict__ vw) {
    __shared__ float sA[16][64 + 4];
    __shared__ float sB[16][64 + 4];

    const int b = blockIdx.z;
    const float* Z = g_z  + b * Pn * Cn;
    float* Z2      = g_z2 + b * Pn * Cn;
    const int tp = blockIdx.y * 64;
    const int tc = blockIdx.x * 64;
    const int tx = threadIdx.x & 15;
    const int ty = threadIdx.x >> 4;

    float acc[4][4] = {};

    for (int k0 = 0; k0 < Cn; k0 += 16) {
        #pragma unroll
        for (int r = 0; r < 4; ++r) {
            const int eI = threadIdx.x + r * 256;
            const int ar = eI >> 4, ak = eI & 15;
            sA[ak][ar] = Z[(tp + ar) * Cn + (k0 + ak)];
            sB[ak][ar] = Wg[(tc + ar) * Cn + (k0 + ak)];
        }
        __syncthreads();
        #pragma unroll
        for (int k = 0; k < 16; ++k) {
            const float4 a4 = *(const float4*)&sA[k][ty * 4];
            const float4 b4 = *(const float4*)&sB[k][tx * 4];
            const float a0[4] = {a4.x, a4.y, a4.z, a4.w};
            const float b0[4] = {b4.x, b4.y, b4.z, b4.w};
            #pragma unroll
            for (int i = 0; i < 4; ++i)
                #pragma unroll
                for (int j = 0; j < 4; ++j)
                    acc[i][j] += a0[i] * b0[j];
        }
        __syncthreads();
    }

    #pragma unroll
    for (int uc = 0; uc < 4; ++uc) {
        const int c = tc + tx * 4 + uc;
        const float inv = gw[c] * rsqrtf(vw[c] + EPSn);
        const float add = bw[c] - mw[c] * inv;
        #pragma unroll
        for (int ui = 0; ui < 4; ++ui) {
            const int p = tp + ty * 4 + ui;
            Z2[p * Cn + c] = fmaxf(acc[ui][uc] * inv + add, 0.0f);
        }
    }
}

// ---------------------------------------------------------------------------
// Scatter: out[b, c, idx[b,p]] = z2[b,p,c].  grid (Pn, Bn), 256 threads (c).
// ---------------------------------------------------------------------------
__global__ void __launch_bounds__(256)
scatter_kernel(float* __restrict__ out) {
    const int b = blockIdx.y;
    const int p = blockIdx.x;
    const int c = threadIdx.x;
    const int col = g_idx[b * Pn + p];
    out[(size_t)b * Cn * HWn + (size_t)c * HWn + (size_t)col] =
        g_z2[((b * Pn + p) << 8) + c];
}

// ---------------------------------------------------------------------------
extern "C" void kernel_launch(void* const* d_in, const int* in_sizes, int n_in,
                              void* d_out, int out_size) {
    const float* x     = (const float*)d_in[0];
    const float* edge  = (const float*)d_in[1];
    const float* w_adj = (const float*)d_in[2];
    const float* g_adj = (const float*)d_in[3];
    const float* b_adj = (const float*)d_in[4];
    const float* m_adj = (const float*)d_in[5];
    const float* v_adj = (const float*)d_in[6];
    const float* w_wg  = (const float*)d_in[7];
    const float* g_wg  = (const float*)d_in[8];
    const float* b_wg  = (const float*)d_in[9];
    const float* m_wg  = (const float*)d_in[10];
    const float* v_wg  = (const float*)d_in[11];
    float* out = (float*)d_out;

    static cudaStream_t s1 = nullptr;
    static cudaEvent_t evA = nullptr, evB = nullptr;
    if (s1 == nullptr) {
        cudaStreamCreateWithFlags(&s1, cudaStreamNonBlocking);
        cudaEventCreateWithFlags(&evA, cudaEventDisableTiming);
        cudaEventCreateWithFlags(&evB, cudaEventDisableTiming);
    }

    // Fork side stream from stream 0.
    cudaEventRecord(evA, 0);
    cudaStreamWaitEvent(s1, evA, 0);

    // Stream 0: bulk copy x -> out on the SMs.
    copy_kernel<<<2048, 256>>>((const float4*)x, (float4*)out);

    // Side stream: exact top-256 via 3x16-bit radix select (chip-wide).
    topk_init<<<192, 1024, 0, s1>>>();
    for (int pass = 2; pass >= 0; --pass) {
        topk_hist<<<dim3(64, Bn), 1024, 0, s1>>>(edge, pass);
        topk_scan<<<Bn, 1024, 0, s1>>>(pass);
    }
    topk_collect<<<dim3(64, Bn), 1024, 0, s1>>>(edge);
    topk_sort<<<Bn, 256, 0, s1>>>();

    // Side stream: gather + GCN stage 1 + GCN stage 2 compute.
    gather_kernel<<<dim3(Pn, Bn), Cn, 0, s1>>>(x);
    gemm1_kernel<<<dim3(4, 4, Bn), 256, 0, s1>>>(w_adj, g_adj, b_adj, m_adj, v_adj);
    gemm2_kernel<<<dim3(4, 4, Bn), 256, 0, s1>>>(w_wg, g_wg, b_wg, m_wg, v_wg);

    // Join and scatter the reasoned point features into out.
    cudaEventRecord(evB, s1);
    cudaStreamWaitEvent(0, evB, 0);
    scatter_kernel<<<dim3(Pn, Bn), 256>>>(out);
}